// round 11
// baseline (speedup 1.0000x reference)
#include <cuda_runtime.h>
#include <cuda_bf16.h>
#include <cstdint>
#include <math.h>

// ---------------------------------------------------------------------------
// Problem constants
#define BB 2048
#define NN 50000
#define CC 768
#define TK 16
#define NCAND 32
#define NPARTS 37
#define NT 11                 // 128-col tiles per part
#define PSPAN (NT*128)        // 1408
#define NPAD (NPARTS*PSPAN)   // 52096
#define NEG_INF __int_as_float(0xff800000)

// Scratch (device globals: no cudaMalloc allowed)
__device__ __nv_bfloat16 g_Ebf[(size_t)NPAD * CC];   // row-scaled by 1/||e||
__device__ __nv_bfloat16 g_Xbf[(size_t)BB * CC];
__device__ __nv_bfloat16 g_S  [(size_t)BB * NPAD];   // screening scores (bf16)
__device__ int    g_cand [(size_t)BB * NCAND];
__device__ double g_csim [(size_t)BB * NCAND];
__device__ int    g_fidx [(size_t)BB * TK];

// ---------------------------------------------------------------------------
// Baseline-PTX helpers (NO sm_103a-gated instructions)
// ---------------------------------------------------------------------------
__device__ __forceinline__ uint32_t smem_u32(const void* p) {
    uint32_t a;
    asm("{ .reg .u64 t; cvta.to.shared.u64 t, %1; cvt.u32.u64 %0, t; }" : "=r"(a) : "l"(p));
    return a;
}
__device__ __forceinline__ void cp16(uint32_t saddr, const void* g) {
    asm volatile("cp.async.cg.shared.global [%0], [%1], 16;" :: "r"(saddr), "l"(g));
}
#define CP_COMMIT() asm volatile("cp.async.commit_group;" ::: "memory")
#define CP_WAIT0()  asm volatile("cp.async.wait_group 0;" ::: "memory")

__device__ __forceinline__ void ldm_x4(uint32_t& r0, uint32_t& r1, uint32_t& r2,
                                       uint32_t& r3, uint32_t a) {
    asm volatile("ldmatrix.sync.aligned.m8n8.x4.shared.b16 {%0,%1,%2,%3}, [%4];"
                 : "=r"(r0), "=r"(r1), "=r"(r2), "=r"(r3) : "r"(a));
}
__device__ __forceinline__ void mma16816(float* c, const uint32_t* a, const uint32_t* b) {
    asm volatile(
        "mma.sync.aligned.m16n8k16.row.col.f32.bf16.bf16.f32 "
        "{%0,%1,%2,%3}, {%4,%5,%6,%7}, {%8,%9}, {%0,%1,%2,%3};"
        : "+f"(c[0]), "+f"(c[1]), "+f"(c[2]), "+f"(c[3])
        : "r"(a[0]), "r"(a[1]), "r"(a[2]), "r"(a[3]), "r"(b[0]), "r"(b[1]));
}

// ---------------------------------------------------------------------------
// Prepass: E -> bf16 scaled by 1/||e|| (rows >= NN zeroed); X -> bf16
// ---------------------------------------------------------------------------
__global__ void prepE_kernel(const float* __restrict__ E) {
    int w = (blockIdx.x * blockDim.x + threadIdx.x) >> 5;
    int lane = threadIdx.x & 31;
    if (w >= NPAD) return;
    uint32_t* orow = reinterpret_cast<uint32_t*>(g_Ebf + (size_t)w * CC);
    if (w >= NN) {
        #pragma unroll
        for (int i = 0; i < 6; i++) { orow[(lane+32*i)*2] = 0u; orow[(lane+32*i)*2+1] = 0u; }
        return;
    }
    const float4* r4 = reinterpret_cast<const float4*>(E + (size_t)w * CC);
    float s = 0.f;
    float4 v[6];
    #pragma unroll
    for (int i = 0; i < 6; i++) {
        v[i] = r4[lane + 32*i];
        s += v[i].x*v[i].x + v[i].y*v[i].y + v[i].z*v[i].z + v[i].w*v[i].w;
    }
    #pragma unroll
    for (int o = 16; o; o >>= 1) s += __shfl_xor_sync(0xffffffffu, s, o);
    float inv = rsqrtf(s);
    #pragma unroll
    for (int i = 0; i < 6; i++) {
        __nv_bfloat162 h0 = __floats2bfloat162_rn(v[i].x*inv, v[i].y*inv);
        __nv_bfloat162 h1 = __floats2bfloat162_rn(v[i].z*inv, v[i].w*inv);
        orow[(lane+32*i)*2]   = *reinterpret_cast<uint32_t*>(&h0);
        orow[(lane+32*i)*2+1] = *reinterpret_cast<uint32_t*>(&h1);
    }
}

__global__ void prepX_kernel(const float* __restrict__ X) {
    int w = (blockIdx.x * blockDim.x + threadIdx.x) >> 5;
    int lane = threadIdx.x & 31;
    if (w >= BB) return;
    const float4* r4 = reinterpret_cast<const float4*>(X + (size_t)w * CC);
    uint32_t* orow = reinterpret_cast<uint32_t*>(g_Xbf + (size_t)w * CC);
    #pragma unroll
    for (int i = 0; i < 6; i++) {
        float4 v = r4[lane + 32*i];
        __nv_bfloat162 h0 = __floats2bfloat162_rn(v.x, v.y);
        __nv_bfloat162 h1 = __floats2bfloat162_rn(v.z, v.w);
        orow[(lane+32*i)*2]   = *reinterpret_cast<uint32_t*>(&h0);
        orow[(lane+32*i)*2+1] = *reinterpret_cast<uint32_t*>(&h1);
    }
}

// Dummy no-op: placed as 3rd launch so ncu (which captures the 4th launch)
// profiles the GEMM kernel.
__global__ void dummy_kernel() {}

// ---------------------------------------------------------------------------
// Kernel 1: PURE bf16 HMMA GEMM (mma.sync m16n8k16), scores -> GMEM (bf16).
// 128x128 CTA tile, 8 warps (2M x 4N), warp tile 64x32, K-chunk 64.
// 2-stage cp.async ring, ONE syncthreads per chunk, fully-unrolled tile loop.
// Epilogue = 16 async STG.32 per thread; no smem staging, no scan, no lists.
// __launch_bounds__(256,2): 2 CTAs/SM. grid(16 Mblk, 37 parts), 256 thr.
// ---------------------------------------------------------------------------
#define STAGE_BYTES 32768              // A 16KB + B 16KB
#define GSMEM       (2*STAGE_BYTES)    // 65,536 B

__global__ void __launch_bounds__(256, 2) gemm_kernel() {
    extern __shared__ char sm[];
    const uint32_t smb = smem_u32(sm);

    const int tid  = threadIdx.x;
    const int warp = tid >> 5;
    const int lane = tid & 31;
    const int m0   = blockIdx.x * 128;
    const int part = blockIdx.y;
    const int pbase = part * PSPAN;

    const int wm = warp & 1;        // 2 M-warps (64 rows each)
    const int wn = warp >> 1;       // 4 N-warps (32 cols each)

    // ---- hoisted cp.async per-thread components
    const int cp_seg = tid & 7;
    uint32_t stA[4];
    const __nv_bfloat16* pAe[4];
    const __nv_bfloat16* pBe[4];
    #pragma unroll
    for (int s = 0; s < 4; s++) {
        int row = (tid >> 3) + 32 * s;
        uint32_t sw = (uint32_t)row * 128 +
                      ((uint32_t)(cp_seg * 16) ^ (((uint32_t)row & 7) << 4));
        uint32_t el = (uint32_t)row * CC + cp_seg * 8;
        stA[s] = smb + sw;
        pAe[s] = g_Xbf + (size_t)m0 * CC + el;
        pBe[s] = g_Ebf + (size_t)pbase * CC + el;
    }

    // ---- hoisted ldmatrix components
    const int a_row = (lane & 15);
    const int a_kh  = (lane >> 4) & 1;
    const int b_nrw = ((lane >> 4) & 1) * 8 + (lane & 7);
    const int b_kh  = (lane >> 3) & 1;
    const uint32_t aB = smb + (uint32_t)(wm * 64 + a_row) * 128;
    const uint32_t bB = smb + 16384 + (uint32_t)(wn * 32 + b_nrw) * 128;
    uint32_t xaK[4], xbK[4];
    #pragma unroll
    for (int ks = 0; ks < 4; ks++) {
        xaK[ks] = ((uint32_t)(ks * 32)) ^ ((uint32_t)(a_kh * 16)) ^ (((uint32_t)a_row & 7) << 4);
        xbK[ks] = ((uint32_t)(ks * 32)) ^ ((uint32_t)(b_kh * 16)) ^ (((uint32_t)b_nrw & 7) << 4);
    }

    // ---- output pointer (bf16x2 units): row m0+wm*64+(lane>>2), col base
    __nv_bfloat16* So = g_S + (size_t)(m0 + wm * 64 + (lane >> 2)) * NPAD
                      + pbase + wn * 32 + (lane & 3) * 2;

    float acc[4][4][4];
    #pragma unroll
    for (int i = 0; i < 4; i++)
        #pragma unroll
        for (int j = 0; j < 4; j++)
            #pragma unroll
            for (int r = 0; r < 4; r++) acc[i][j][r] = 0.f;

    // prologue: issue chunk (t=0, c=0) into stage 0
    #pragma unroll
    for (int s = 0; s < 4; s++) {
        cp16(stA[s],         pAe[s]);
        cp16(stA[s] + 16384, pBe[s]);
    }
    CP_COMMIT();

    for (int t = 0; t < NT; t++) {
        #pragma unroll
        for (int c = 0; c < 12; c++) {
            CP_WAIT0();          // current chunk (t,c) resident
            __syncthreads();     // all warps done with previous chunk's stage
            if (c < 11) {
                const uint32_t so = (uint32_t)(((c + 1) & 1) * 32768);
                #pragma unroll
                for (int s = 0; s < 4; s++) {
                    cp16(stA[s] + so,         pAe[s] + (c + 1) * 64);
                    cp16(stA[s] + so + 16384, pBe[s] + (c + 1) * 64);
                }
            } else if (t + 1 < NT) {
                #pragma unroll
                for (int s = 0; s < 4; s++) {
                    cp16(stA[s],         pAe[s]);
                    cp16(stA[s] + 16384, pBe[s] + 128 * CC);
                }
            }
            CP_COMMIT();

            // compute chunk (t,c) from stage c&1 (compile-time)
            const uint32_t so = (uint32_t)((c & 1) * 32768);
            #pragma unroll
            for (int ks = 0; ks < 4; ks++) {
                const uint32_t ax = aB + so + xaK[ks];
                const uint32_t bx = bB + so + xbK[ks];
                uint32_t a[4][4], b[2][4];
                #pragma unroll
                for (int i = 0; i < 4; i++)
                    ldm_x4(a[i][0], a[i][1], a[i][2], a[i][3], ax + i * 2048);
                #pragma unroll
                for (int j16 = 0; j16 < 2; j16++)
                    ldm_x4(b[j16][0], b[j16][1], b[j16][2], b[j16][3], bx + j16 * 2048);
                #pragma unroll
                for (int i = 0; i < 4; i++)
                    #pragma unroll
                    for (int j2 = 0; j2 < 4; j2++)
                        mma16816(acc[i][j2], a[i], &b[j2 >> 1][(j2 & 1) * 2]);
            }
        }

        // advance B tile pointers
        #pragma unroll
        for (int s = 0; s < 4; s++) pBe[s] += 128 * CC;

        // ---- epilogue: async bf16 stores straight to GMEM
        #pragma unroll
        for (int i = 0; i < 4; i++) {
            #pragma unroll
            for (int j2 = 0; j2 < 4; j2++) {
                __nv_bfloat162 p0 = __floats2bfloat162_rn(acc[i][j2][0], acc[i][j2][1]);
                __nv_bfloat162 p1 = __floats2bfloat162_rn(acc[i][j2][2], acc[i][j2][3]);
                *reinterpret_cast<__nv_bfloat162*>(So + (size_t)(i * 16) * NPAD + j2 * 8)     = p0;
                *reinterpret_cast<__nv_bfloat162*>(So + (size_t)(i * 16 + 8) * NPAD + j2 * 8) = p1;
                acc[i][j2][0] = 0.f; acc[i][j2][1] = 0.f;
                acc[i][j2][2] = 0.f; acc[i][j2][3] = 0.f;
            }
        }
        So += 128;   // next 128-col tile
    }
}

// ---------------------------------------------------------------------------
// Kernel 2: streaming top-k scan. One WARP per row; lane-local top-16 over
// 1628 cols (coalesced 512B warp reads), then warp-merge 512 -> top-32 pool.
// ---------------------------------------------------------------------------
__global__ void scan_topk_kernel() {
    const int row  = blockIdx.x * 8 + (threadIdx.x >> 5);
    const int lane = threadIdx.x & 31;

    const uint4* p = reinterpret_cast<const uint4*>(g_S + (size_t)row * NPAD);

    float tvv[TK]; int tii[TK];
    #pragma unroll
    for (int q = 0; q < TK; q++) { tvv[q] = NEG_INF; tii[q] = 0x7fffffff; }
    float mv = NEG_INF; int mp = 0;

    // cols processed: i in [0,196); i==195 only lanes<10 (exactly covers NN)
    const int imax = (lane < 10) ? 196 : 195;
    for (int i = 0; i < imax; i++) {
        uint4 raw = p[i * 32 + lane];
        __nv_bfloat162 h0 = *reinterpret_cast<__nv_bfloat162*>(&raw.x);
        __nv_bfloat162 h1 = *reinterpret_cast<__nv_bfloat162*>(&raw.y);
        __nv_bfloat162 h2 = *reinterpret_cast<__nv_bfloat162*>(&raw.z);
        __nv_bfloat162 h3 = *reinterpret_cast<__nv_bfloat162*>(&raw.w);
        __nv_bfloat162 m01 = __hmax2(h0, h1);
        __nv_bfloat162 m23 = __hmax2(h2, h3);
        __nv_bfloat162 m   = __hmax2(m01, m23);
        float mx = fmaxf(__bfloat162float(m.x), __bfloat162float(m.y));
        if (mx > mv) {
            const int cbase = i * 256 + lane * 8;
            float f[8];
            f[0] = __bfloat162float(h0.x); f[1] = __bfloat162float(h0.y);
            f[2] = __bfloat162float(h1.x); f[3] = __bfloat162float(h1.y);
            f[4] = __bfloat162float(h2.x); f[5] = __bfloat162float(h2.y);
            f[6] = __bfloat162float(h3.x); f[7] = __bfloat162float(h3.y);
            #pragma unroll
            for (int u = 0; u < 8; u++) {
                if (f[u] > mv) {
                    #pragma unroll
                    for (int q = 0; q < TK; q++)
                        if (q == mp) { tvv[q] = f[u]; tii[q] = cbase + u; }
                    mv = tvv[0]; mp = 0; int mi = tii[0];
                    #pragma unroll
                    for (int q = 1; q < TK; q++) {
                        if (tvv[q] < mv || (tvv[q] == mv && tii[q] > mi)) {
                            mv = tvv[q]; mp = q; mi = tii[q];
                        }
                    }
                }
            }
        }
    }

    // warp merge: 32 lanes x 16 -> global top-32 candidate pool
    for (int rnd = 0; rnd < NCAND; rnd++) {
        float bv = NEG_INF; int bi = 0x7fffffff; int bs = -1;
        #pragma unroll
        for (int q = 0; q < TK; q++)
            if (tvv[q] > bv || (tvv[q] == bv && tii[q] < bi)) { bv = tvv[q]; bi = tii[q]; bs = q; }
        float wv = bv; int wi = bi;
        #pragma unroll
        for (int o = 16; o; o >>= 1) {
            float ov = __shfl_xor_sync(0xffffffffu, wv, o);
            int   oi = __shfl_xor_sync(0xffffffffu, wi, o);
            if (ov > wv || (ov == wv && oi < wi)) { wv = ov; wi = oi; }
        }
        if (bs >= 0 && bv == wv && bi == wi) {
            #pragma unroll
            for (int q = 0; q < TK; q++)
                if (q == bs) { tvv[q] = NEG_INF; tii[q] = 0x7fffffff; }
        }
        if (lane == 0) g_cand[row * NCAND + rnd] = wi;
    }
}

// ---------------------------------------------------------------------------
// Kernel 2.5a: fp64 exact sims — one WARP per (row, candidate)
// ---------------------------------------------------------------------------
__global__ void refine_dot_kernel(const float* __restrict__ X, const float* __restrict__ E) {
    const int gw   = blockIdx.x * 8 + (threadIdx.x >> 5);
    const int lane = threadIdx.x & 31;
    const int row  = gw >> 5;
    const int slot = gw & 31;
    if (row >= BB) return;
    const int cand = g_cand[row * NCAND + slot];
    const float4* x4 = reinterpret_cast<const float4*>(X + (size_t)row  * CC);
    const float4* e4 = reinterpret_cast<const float4*>(E + (size_t)cand * CC);

    double dot = 0.0, e2 = 0.0;
    #pragma unroll
    for (int i = 0; i < 6; i++) {
        float4 xv = x4[lane + 32 * i];
        float4 ev = e4[lane + 32 * i];
        dot = fma((double)xv.x, (double)ev.x, dot);
        e2  = fma((double)ev.x, (double)ev.x, e2);
        dot = fma((double)xv.y, (double)ev.y, dot);
        e2  = fma((double)ev.y, (double)ev.y, e2);
        dot = fma((double)xv.z, (double)ev.z, dot);
        e2  = fma((double)ev.z, (double)ev.z, e2);
        dot = fma((double)xv.w, (double)ev.w, dot);
        e2  = fma((double)ev.w, (double)ev.w, e2);
    }
    #pragma unroll
    for (int o = 16; o; o >>= 1) {
        dot += __shfl_xor_sync(0xffffffffu, dot, o);
        e2  += __shfl_xor_sync(0xffffffffu, e2,  o);
    }
    if (lane == 0) g_csim[row * NCAND + slot] = dot / sqrt(e2);
}

// Kernel 2.5b: sorted top-16 of the 32 exact sims (warp per row)
__global__ void refine_select_kernel() {
    const int warp = threadIdx.x >> 5;
    const int lane = threadIdx.x & 31;
    const int row  = blockIdx.x * 8 + warp;
    if (row >= BB) return;

    double v = g_csim[row * NCAND + lane];
    int  idx = g_cand[row * NCAND + lane];
    for (int rnd = 0; rnd < TK; rnd++) {
        double wv = v; int wi = idx;
        #pragma unroll
        for (int o = 16; o; o >>= 1) {
            double ov = __shfl_xor_sync(0xffffffffu, wv, o);
            int    oi = __shfl_xor_sync(0xffffffffu, wi, o);
            if (ov > wv || (ov == wv && oi < wi)) { wv = ov; wi = oi; }
        }
        if (idx == wi) { v = -INFINITY; idx = 0x7fffffff; }
        if (lane == 0) g_fidx[row * TK + rnd] = wi;
    }
}

// ---------------------------------------------------------------------------
// Kernel 3: gather with reference's reshape(-1,B,C).transpose(1,0,2) scramble
// ---------------------------------------------------------------------------
__global__ void gather_kernel(const float* __restrict__ E, float* __restrict__ out) {
    const int bj = blockIdx.x;        // b*16 + j
    const int b = bj >> 4, j = bj & 15;
    const int src_row  = j * (BB / TK) + (b >> 4);
    const int src_slot = b & 15;
    const int src = g_fidx[src_row * TK + src_slot];
    const float4* s4 = reinterpret_cast<const float4*>(E + (size_t)src * CC);
    float4* d4 = reinterpret_cast<float4*>(out + (size_t)bj * CC);
    d4[threadIdx.x] = s4[threadIdx.x];
}

// ---------------------------------------------------------------------------
extern "C" void kernel_launch(void* const* d_in, const int* in_sizes, int n_in,
                              void* d_out, int out_size) {
    const float* X = (const float*)d_in[0];
    const float* E = (const float*)d_in[1];
    float* out = (float*)d_out;
    (void)in_sizes; (void)n_in; (void)out_size;

    cudaFuncSetAttribute(gemm_kernel,
                         cudaFuncAttributeMaxDynamicSharedMemorySize, GSMEM);

    prepE_kernel<<<NPAD / 8, 256>>>(E);     // launch 1
    prepX_kernel<<<BB / 8, 256>>>(X);       // launch 2
    dummy_kernel<<<1, 32>>>();              // launch 3 (so gemm is 4th -> profiled)
    gemm_kernel<<<dim3(16, NPARTS), 256, GSMEM>>>();   // launch 4
    scan_topk_kernel<<<BB / 8, 256>>>();
    refine_dot_kernel<<<BB * NCAND / 8, 256>>>(X, E);
    refine_select_kernel<<<BB / 8, 256>>>();
    gather_kernel<<<BB * TK, 192>>>(E, out);
}

// round 12
// speedup vs baseline: 1.5203x; 1.5203x over previous
#include <cuda_runtime.h>
#include <cuda_bf16.h>
#include <cstdint>
#include <math.h>

// ---------------------------------------------------------------------------
// Problem constants
#define BB 2048
#define NN 50000
#define CC 768
#define TK 16
#define NCAND 32
#define NPARTS 37
#define NT 11                 // 128-col tiles per part
#define PSPAN (NT*128)        // 1408
#define NPAD (NPARTS*PSPAN)   // 52096
#define NEG_INF __int_as_float(0xff800000)

// Scratch (device globals: no cudaMalloc allowed)
__device__ __nv_bfloat16 g_Ebf[(size_t)NPAD * CC];   // row-scaled by 1/||e||
__device__ __nv_bfloat16 g_Xbf[(size_t)BB * CC];
__device__ __nv_bfloat16 g_S  [(size_t)BB * NPAD];   // screening scores (bf16)
__device__ int    g_cand [(size_t)BB * NCAND];
__device__ double g_csim [(size_t)BB * NCAND];
__device__ int    g_fidx [(size_t)BB * TK];

// ---------------------------------------------------------------------------
// Baseline-PTX helpers (NO sm_103a-gated instructions)
// ---------------------------------------------------------------------------
__device__ __forceinline__ uint32_t smem_u32(const void* p) {
    uint32_t a;
    asm("{ .reg .u64 t; cvta.to.shared.u64 t, %1; cvt.u32.u64 %0, t; }" : "=r"(a) : "l"(p));
    return a;
}
__device__ __forceinline__ void cp16(uint32_t saddr, const void* g) {
    asm volatile("cp.async.cg.shared.global [%0], [%1], 16;" :: "r"(saddr), "l"(g));
}
#define CP_COMMIT() asm volatile("cp.async.commit_group;" ::: "memory")
#define CP_WAIT0()  asm volatile("cp.async.wait_group 0;" ::: "memory")

__device__ __forceinline__ void ldm_x4(uint32_t& r0, uint32_t& r1, uint32_t& r2,
                                       uint32_t& r3, uint32_t a) {
    asm volatile("ldmatrix.sync.aligned.m8n8.x4.shared.b16 {%0,%1,%2,%3}, [%4];"
                 : "=r"(r0), "=r"(r1), "=r"(r2), "=r"(r3) : "r"(a));
}
__device__ __forceinline__ void mma16816(float* c, const uint32_t* a, const uint32_t* b) {
    asm volatile(
        "mma.sync.aligned.m16n8k16.row.col.f32.bf16.bf16.f32 "
        "{%0,%1,%2,%3}, {%4,%5,%6,%7}, {%8,%9}, {%0,%1,%2,%3};"
        : "+f"(c[0]), "+f"(c[1]), "+f"(c[2]), "+f"(c[3])
        : "r"(a[0]), "r"(a[1]), "r"(a[2]), "r"(a[3]), "r"(b[0]), "r"(b[1]));
}

// ---------------------------------------------------------------------------
// Prepass: E -> bf16 scaled by 1/||e|| (rows >= NN zeroed); X -> bf16
// ---------------------------------------------------------------------------
__global__ void prepE_kernel(const float* __restrict__ E) {
    int w = (blockIdx.x * blockDim.x + threadIdx.x) >> 5;
    int lane = threadIdx.x & 31;
    if (w >= NPAD) return;
    uint32_t* orow = reinterpret_cast<uint32_t*>(g_Ebf + (size_t)w * CC);
    if (w >= NN) {
        #pragma unroll
        for (int i = 0; i < 6; i++) { orow[(lane+32*i)*2] = 0u; orow[(lane+32*i)*2+1] = 0u; }
        return;
    }
    const float4* r4 = reinterpret_cast<const float4*>(E + (size_t)w * CC);
    float s = 0.f;
    float4 v[6];
    #pragma unroll
    for (int i = 0; i < 6; i++) {
        v[i] = r4[lane + 32*i];
        s += v[i].x*v[i].x + v[i].y*v[i].y + v[i].z*v[i].z + v[i].w*v[i].w;
    }
    #pragma unroll
    for (int o = 16; o; o >>= 1) s += __shfl_xor_sync(0xffffffffu, s, o);
    float inv = rsqrtf(s);
    #pragma unroll
    for (int i = 0; i < 6; i++) {
        __nv_bfloat162 h0 = __floats2bfloat162_rn(v[i].x*inv, v[i].y*inv);
        __nv_bfloat162 h1 = __floats2bfloat162_rn(v[i].z*inv, v[i].w*inv);
        orow[(lane+32*i)*2]   = *reinterpret_cast<uint32_t*>(&h0);
        orow[(lane+32*i)*2+1] = *reinterpret_cast<uint32_t*>(&h1);
    }
}

__global__ void prepX_kernel(const float* __restrict__ X) {
    int w = (blockIdx.x * blockDim.x + threadIdx.x) >> 5;
    int lane = threadIdx.x & 31;
    if (w >= BB) return;
    const float4* r4 = reinterpret_cast<const float4*>(X + (size_t)w * CC);
    uint32_t* orow = reinterpret_cast<uint32_t*>(g_Xbf + (size_t)w * CC);
    #pragma unroll
    for (int i = 0; i < 6; i++) {
        float4 v = r4[lane + 32*i];
        __nv_bfloat162 h0 = __floats2bfloat162_rn(v.x, v.y);
        __nv_bfloat162 h1 = __floats2bfloat162_rn(v.z, v.w);
        orow[(lane+32*i)*2]   = *reinterpret_cast<uint32_t*>(&h0);
        orow[(lane+32*i)*2+1] = *reinterpret_cast<uint32_t*>(&h1);
    }
}

// ---------------------------------------------------------------------------
// Kernel 1: PURE bf16 HMMA GEMM (mma.sync m16n8k16), scores -> GMEM (bf16).
// Identical to R11 (365us, tensor=73.5%).
// ---------------------------------------------------------------------------
#define STAGE_BYTES 32768              // A 16KB + B 16KB
#define GSMEM       (2*STAGE_BYTES)    // 65,536 B

__global__ void __launch_bounds__(256, 2) gemm_kernel() {
    extern __shared__ char sm[];
    const uint32_t smb = smem_u32(sm);

    const int tid  = threadIdx.x;
    const int warp = tid >> 5;
    const int lane = tid & 31;
    const int m0   = blockIdx.x * 128;
    const int part = blockIdx.y;
    const int pbase = part * PSPAN;

    const int wm = warp & 1;        // 2 M-warps (64 rows each)
    const int wn = warp >> 1;       // 4 N-warps (32 cols each)

    // ---- hoisted cp.async per-thread components
    const int cp_seg = tid & 7;
    uint32_t stA[4];
    const __nv_bfloat16* pAe[4];
    const __nv_bfloat16* pBe[4];
    #pragma unroll
    for (int s = 0; s < 4; s++) {
        int row = (tid >> 3) + 32 * s;
        uint32_t sw = (uint32_t)row * 128 +
                      ((uint32_t)(cp_seg * 16) ^ (((uint32_t)row & 7) << 4));
        uint32_t el = (uint32_t)row * CC + cp_seg * 8;
        stA[s] = smb + sw;
        pAe[s] = g_Xbf + (size_t)m0 * CC + el;
        pBe[s] = g_Ebf + (size_t)pbase * CC + el;
    }

    // ---- hoisted ldmatrix components
    const int a_row = (lane & 15);
    const int a_kh  = (lane >> 4) & 1;
    const int b_nrw = ((lane >> 4) & 1) * 8 + (lane & 7);
    const int b_kh  = (lane >> 3) & 1;
    const uint32_t aB = smb + (uint32_t)(wm * 64 + a_row) * 128;
    const uint32_t bB = smb + 16384 + (uint32_t)(wn * 32 + b_nrw) * 128;
    uint32_t xaK[4], xbK[4];
    #pragma unroll
    for (int ks = 0; ks < 4; ks++) {
        xaK[ks] = ((uint32_t)(ks * 32)) ^ ((uint32_t)(a_kh * 16)) ^ (((uint32_t)a_row & 7) << 4);
        xbK[ks] = ((uint32_t)(ks * 32)) ^ ((uint32_t)(b_kh * 16)) ^ (((uint32_t)b_nrw & 7) << 4);
    }

    // ---- output pointer: row m0+wm*64+(lane>>2), col base
    __nv_bfloat16* So = g_S + (size_t)(m0 + wm * 64 + (lane >> 2)) * NPAD
                      + pbase + wn * 32 + (lane & 3) * 2;

    float acc[4][4][4];
    #pragma unroll
    for (int i = 0; i < 4; i++)
        #pragma unroll
        for (int j = 0; j < 4; j++)
            #pragma unroll
            for (int r = 0; r < 4; r++) acc[i][j][r] = 0.f;

    // prologue: issue chunk (t=0, c=0) into stage 0
    #pragma unroll
    for (int s = 0; s < 4; s++) {
        cp16(stA[s],         pAe[s]);
        cp16(stA[s] + 16384, pBe[s]);
    }
    CP_COMMIT();

    for (int t = 0; t < NT; t++) {
        #pragma unroll
        for (int c = 0; c < 12; c++) {
            CP_WAIT0();
            __syncthreads();
            if (c < 11) {
                const uint32_t so = (uint32_t)(((c + 1) & 1) * 32768);
                #pragma unroll
                for (int s = 0; s < 4; s++) {
                    cp16(stA[s] + so,         pAe[s] + (c + 1) * 64);
                    cp16(stA[s] + so + 16384, pBe[s] + (c + 1) * 64);
                }
            } else if (t + 1 < NT) {
                #pragma unroll
                for (int s = 0; s < 4; s++) {
                    cp16(stA[s],         pAe[s]);
                    cp16(stA[s] + 16384, pBe[s] + 128 * CC);
                }
            }
            CP_COMMIT();

            const uint32_t so = (uint32_t)((c & 1) * 32768);
            #pragma unroll
            for (int ks = 0; ks < 4; ks++) {
                const uint32_t ax = aB + so + xaK[ks];
                const uint32_t bx = bB + so + xbK[ks];
                uint32_t a[4][4], b[2][4];
                #pragma unroll
                for (int i = 0; i < 4; i++)
                    ldm_x4(a[i][0], a[i][1], a[i][2], a[i][3], ax + i * 2048);
                #pragma unroll
                for (int j16 = 0; j16 < 2; j16++)
                    ldm_x4(b[j16][0], b[j16][1], b[j16][2], b[j16][3], bx + j16 * 2048);
                #pragma unroll
                for (int i = 0; i < 4; i++)
                    #pragma unroll
                    for (int j2 = 0; j2 < 4; j2++)
                        mma16816(acc[i][j2], a[i], &b[j2 >> 1][(j2 & 1) * 2]);
            }
        }

        #pragma unroll
        for (int s = 0; s < 4; s++) pBe[s] += 128 * CC;

        // ---- epilogue: bf16 stores straight to GMEM
        #pragma unroll
        for (int i = 0; i < 4; i++) {
            #pragma unroll
            for (int j2 = 0; j2 < 4; j2++) {
                __nv_bfloat162 p0 = __floats2bfloat162_rn(acc[i][j2][0], acc[i][j2][1]);
                __nv_bfloat162 p1 = __floats2bfloat162_rn(acc[i][j2][2], acc[i][j2][3]);
                *reinterpret_cast<__nv_bfloat162*>(So + (size_t)(i * 16) * NPAD + j2 * 8)     = p0;
                *reinterpret_cast<__nv_bfloat162*>(So + (size_t)(i * 16 + 8) * NPAD + j2 * 8) = p1;
                acc[i][j2][0] = 0.f; acc[i][j2][1] = 0.f;
                acc[i][j2][2] = 0.f; acc[i][j2][3] = 0.f;
            }
        }
        So += 128;   // next 128-col tile
    }
}

// ---------------------------------------------------------------------------
// Kernel 2: parallel top-k scan. One BLOCK (256 thr) per row.
// Thread reads uint4 at idx=i*256+tid (coalesced); valid idx < 6250
// (6250*8 = 50000 exactly). Per-thread top-8 regs + bf16 fast-reject,
// then warp top-32 and cross-warp top-32 -> g_cand.
// ---------------------------------------------------------------------------
#define PT 8    // per-thread list size

__global__ void __launch_bounds__(256, 4) scan_topk_kernel() {
    __shared__ float swv[8 * NCAND];
    __shared__ int   swi[8 * NCAND];

    const int row  = blockIdx.x;
    const int tid  = threadIdx.x;
    const int warp = tid >> 5;
    const int lane = tid & 31;

    const uint4* p = reinterpret_cast<const uint4*>(g_S + (size_t)row * NPAD);

    float tv[PT]; int ti[PT];
    #pragma unroll
    for (int q = 0; q < PT; q++) { tv[q] = NEG_INF; ti[q] = 0x7fffffff; }
    float mv = NEG_INF; int mp = 0;

    // idx < 6250: i in [0,24) all threads; i==24 only tid<106
    const int imax = (tid < 106) ? 25 : 24;
    for (int i = 0; i < imax; i++) {
        const int idx = i * 256 + tid;
        uint4 raw = p[idx];
        __nv_bfloat162 h0 = *reinterpret_cast<__nv_bfloat162*>(&raw.x);
        __nv_bfloat162 h1 = *reinterpret_cast<__nv_bfloat162*>(&raw.y);
        __nv_bfloat162 h2 = *reinterpret_cast<__nv_bfloat162*>(&raw.z);
        __nv_bfloat162 h3 = *reinterpret_cast<__nv_bfloat162*>(&raw.w);
        __nv_bfloat162 m = __hmax2(__hmax2(h0, h1), __hmax2(h2, h3));
        float mx = fmaxf(__bfloat162float(m.x), __bfloat162float(m.y));
        if (mx > mv) {
            const int cbase = idx * 8;
            float f[8];
            f[0] = __bfloat162float(h0.x); f[1] = __bfloat162float(h0.y);
            f[2] = __bfloat162float(h1.x); f[3] = __bfloat162float(h1.y);
            f[4] = __bfloat162float(h2.x); f[5] = __bfloat162float(h2.y);
            f[6] = __bfloat162float(h3.x); f[7] = __bfloat162float(h3.y);
            #pragma unroll
            for (int u = 0; u < 8; u++) {
                if (f[u] > mv) {
                    #pragma unroll
                    for (int q = 0; q < PT; q++)
                        if (q == mp) { tv[q] = f[u]; ti[q] = cbase + u; }
                    mv = tv[0]; mp = 0; int mi = ti[0];
                    #pragma unroll
                    for (int q = 1; q < PT; q++) {
                        if (tv[q] < mv || (tv[q] == mv && ti[q] > mi)) {
                            mv = tv[q]; mp = q; mi = ti[q];
                        }
                    }
                }
            }
        }
    }

    // warp-level top-32 of 32 lanes x 8 entries
    for (int rnd = 0; rnd < NCAND; rnd++) {
        float bv = NEG_INF; int bi = 0x7fffffff; int bs = -1;
        #pragma unroll
        for (int q = 0; q < PT; q++)
            if (tv[q] > bv || (tv[q] == bv && ti[q] < bi)) { bv = tv[q]; bi = ti[q]; bs = q; }
        float wv = bv; int wi = bi;
        #pragma unroll
        for (int o = 16; o; o >>= 1) {
            float ov = __shfl_xor_sync(0xffffffffu, wv, o);
            int   oi = __shfl_xor_sync(0xffffffffu, wi, o);
            if (ov > wv || (ov == wv && oi < wi)) { wv = ov; wi = oi; }
        }
        if (bs >= 0 && bv == wv && bi == wi) {
            #pragma unroll
            for (int q = 0; q < PT; q++)
                if (q == bs) { tv[q] = NEG_INF; ti[q] = 0x7fffffff; }
        }
        if (lane == 0) { swv[warp * NCAND + rnd] = wv; swi[warp * NCAND + rnd] = wi; }
    }
    __syncthreads();

    // final: warp 0 merges 8x32 = 256 entries -> top-32 pool
    if (warp == 0) {
        float ev[8]; int ei[8];
        #pragma unroll
        for (int j = 0; j < 8; j++) { ev[j] = swv[lane * 8 + j]; ei[j] = swi[lane * 8 + j]; }
        for (int rnd = 0; rnd < NCAND; rnd++) {
            float bv = NEG_INF; int bi = 0x7fffffff; int bs = -1;
            #pragma unroll
            for (int j = 0; j < 8; j++)
                if (ev[j] > bv || (ev[j] == bv && ei[j] < bi)) { bv = ev[j]; bi = ei[j]; bs = j; }
            float wv = bv; int wi = bi;
            #pragma unroll
            for (int o = 16; o; o >>= 1) {
                float ov = __shfl_xor_sync(0xffffffffu, wv, o);
                int   oi = __shfl_xor_sync(0xffffffffu, wi, o);
                if (ov > wv || (ov == wv && oi < wi)) { wv = ov; wi = oi; }
            }
            if (bs >= 0 && bv == wv && bi == wi) {
                #pragma unroll
                for (int j = 0; j < 8; j++)
                    if (j == bs) { ev[j] = NEG_INF; ei[j] = 0x7fffffff; }
            }
            if (lane == 0) g_cand[row * NCAND + rnd] = wi;
        }
    }
}

// ---------------------------------------------------------------------------
// Kernel 2.5a: fp64 exact sims — one WARP per (row, candidate)
// ---------------------------------------------------------------------------
__global__ void refine_dot_kernel(const float* __restrict__ X, const float* __restrict__ E) {
    const int gw   = blockIdx.x * 8 + (threadIdx.x >> 5);
    const int lane = threadIdx.x & 31;
    const int row  = gw >> 5;
    const int slot = gw & 31;
    if (row >= BB) return;
    const int cand = g_cand[row * NCAND + slot];
    const float4* x4 = reinterpret_cast<const float4*>(X + (size_t)row  * CC);
    const float4* e4 = reinterpret_cast<const float4*>(E + (size_t)cand * CC);

    double dot = 0.0, e2 = 0.0;
    #pragma unroll
    for (int i = 0; i < 6; i++) {
        float4 xv = x4[lane + 32 * i];
        float4 ev = e4[lane + 32 * i];
        dot = fma((double)xv.x, (double)ev.x, dot);
        e2  = fma((double)ev.x, (double)ev.x, e2);
        dot = fma((double)xv.y, (double)ev.y, dot);
        e2  = fma((double)ev.y, (double)ev.y, e2);
        dot = fma((double)xv.z, (double)ev.z, dot);
        e2  = fma((double)ev.z, (double)ev.z, e2);
        dot = fma((double)xv.w, (double)ev.w, dot);
        e2  = fma((double)ev.w, (double)ev.w, e2);
    }
    #pragma unroll
    for (int o = 16; o; o >>= 1) {
        dot += __shfl_xor_sync(0xffffffffu, dot, o);
        e2  += __shfl_xor_sync(0xffffffffu, e2,  o);
    }
    if (lane == 0) g_csim[row * NCAND + slot] = dot / sqrt(e2);
}

// Kernel 2.5b: sorted top-16 of the 32 exact sims (warp per row)
__global__ void refine_select_kernel() {
    const int warp = threadIdx.x >> 5;
    const int lane = threadIdx.x & 31;
    const int row  = blockIdx.x * 8 + warp;
    if (row >= BB) return;

    double v = g_csim[row * NCAND + lane];
    int  idx = g_cand[row * NCAND + lane];
    for (int rnd = 0; rnd < TK; rnd++) {
        double wv = v; int wi = idx;
        #pragma unroll
        for (int o = 16; o; o >>= 1) {
            double ov = __shfl_xor_sync(0xffffffffu, wv, o);
            int    oi = __shfl_xor_sync(0xffffffffu, wi, o);
            if (ov > wv || (ov == wv && oi < wi)) { wv = ov; wi = oi; }
        }
        if (idx == wi) { v = -INFINITY; idx = 0x7fffffff; }
        if (lane == 0) g_fidx[row * TK + rnd] = wi;
    }
}

// ---------------------------------------------------------------------------
// Kernel 3: gather with reference's reshape(-1,B,C).transpose(1,0,2) scramble
// ---------------------------------------------------------------------------
__global__ void gather_kernel(const float* __restrict__ E, float* __restrict__ out) {
    const int bj = blockIdx.x;        // b*16 + j
    const int b = bj >> 4, j = bj & 15;
    const int src_row  = j * (BB / TK) + (b >> 4);
    const int src_slot = b & 15;
    const int src = g_fidx[src_row * TK + src_slot];
    const float4* s4 = reinterpret_cast<const float4*>(E + (size_t)src * CC);
    float4* d4 = reinterpret_cast<float4*>(out + (size_t)bj * CC);
    d4[threadIdx.x] = s4[threadIdx.x];
}

// ---------------------------------------------------------------------------
extern "C" void kernel_launch(void* const* d_in, const int* in_sizes, int n_in,
                              void* d_out, int out_size) {
    const float* X = (const float*)d_in[0];
    const float* E = (const float*)d_in[1];
    float* out = (float*)d_out;
    (void)in_sizes; (void)n_in; (void)out_size;

    cudaFuncSetAttribute(gemm_kernel,
                         cudaFuncAttributeMaxDynamicSharedMemorySize, GSMEM);

    prepE_kernel<<<NPAD / 8, 256>>>(E);                // launch 1
    prepX_kernel<<<BB / 8, 256>>>(X);                  // launch 2
    gemm_kernel<<<dim3(16, NPARTS), 256, GSMEM>>>();   // launch 3
    scan_topk_kernel<<<BB, 256>>>();                   // launch 4 (profiled)
    refine_dot_kernel<<<BB * NCAND / 8, 256>>>(X, E);
    refine_select_kernel<<<BB / 8, 256>>>();
    gather_kernel<<<BB * TK, 192>>>(E, out);
}